// round 1
// baseline (speedup 1.0000x reference)
#include <cuda_runtime.h>
#include <cuda_bf16.h>
#include <math.h>

// Problem constants
#define BB 8
#define NN 384
#define DIN 512
#define DM 512

// Device scratch (allocation-free requirement -> __device__ globals)
__device__ float g_q[BB * NN * DM];        // 6 MB
__device__ float g_k[BB * NN * DM];        // 6 MB
__device__ float g_left[BB * NN];
__device__ float g_right[BB * NN];
__device__ float g_logp[BB * NN * NN];     // 4.7 MB
__device__ float g_log1mp[BB * NN * NN];   // 4.7 MB

// ---------------------------------------------------------------------------
// Kernel 1: q = h @ Wq^T + bq ; k = h @ Wk^T   (z=0 -> q, z=1 -> k)
// C is (B*N=3072) x 512, A = h (3072x512), W row-major (512 x 512), both
// K-contiguous. 64x64 tiles, K-chunk 16, 256 threads, 4x4 per thread.
// ---------------------------------------------------------------------------
__global__ void __launch_bounds__(256) proj_gemm(
    const float* __restrict__ h,
    const float* __restrict__ Wq, const float* __restrict__ bq,
    const float* __restrict__ Wk)
{
    const int z = blockIdx.z;
    const float* __restrict__ W = z ? Wk : Wq;
    float* __restrict__ out = z ? g_k : g_q;

    __shared__ float As[16][68];
    __shared__ float Bs[16][68];

    const int m0 = blockIdx.y * 64;
    const int o0 = blockIdx.x * 64;
    const int tid = threadIdx.x;
    const int lr = tid >> 2;       // 0..63 load row
    const int lc = tid & 3;        // 0..3  k-float4
    const int tx = tid & 15;       // 0..15 -> j micro
    const int ty = tid >> 4;       // 0..15 -> i micro

    float acc[4][4];
#pragma unroll
    for (int a = 0; a < 4; a++)
#pragma unroll
        for (int b = 0; b < 4; b++) acc[a][b] = 0.f;

    for (int k0 = 0; k0 < DIN; k0 += 16) {
        float4 av = *(const float4*)&h[(size_t)(m0 + lr) * DIN + k0 + lc * 4];
        float4 bv = *(const float4*)&W[(size_t)(o0 + lr) * DIN + k0 + lc * 4];
        As[lc * 4 + 0][lr] = av.x; As[lc * 4 + 1][lr] = av.y;
        As[lc * 4 + 2][lr] = av.z; As[lc * 4 + 3][lr] = av.w;
        Bs[lc * 4 + 0][lr] = bv.x; Bs[lc * 4 + 1][lr] = bv.y;
        Bs[lc * 4 + 2][lr] = bv.z; Bs[lc * 4 + 3][lr] = bv.w;
        __syncthreads();
#pragma unroll
        for (int kk = 0; kk < 16; kk++) {
            float ar[4], br[4];
#pragma unroll
            for (int ii = 0; ii < 4; ii++) ar[ii] = As[kk][ty * 4 + ii];
#pragma unroll
            for (int jj = 0; jj < 4; jj++) br[jj] = Bs[kk][tx * 4 + jj];
#pragma unroll
            for (int ii = 0; ii < 4; ii++)
#pragma unroll
                for (int jj = 0; jj < 4; jj++)
                    acc[ii][jj] = fmaf(ar[ii], br[jj], acc[ii][jj]);
        }
        __syncthreads();
    }

    float bias[4];
#pragma unroll
    for (int jj = 0; jj < 4; jj++)
        bias[jj] = z ? 0.f : bq[o0 + tx * 4 + jj];

#pragma unroll
    for (int ii = 0; ii < 4; ii++) {
        const int m = m0 + ty * 4 + ii;
#pragma unroll
        for (int jj = 0; jj < 4; jj++) {
            const int o = o0 + tx * 4 + jj;
            out[(size_t)m * DM + o] = acc[ii][jj] + bias[jj];
        }
    }
}

// ---------------------------------------------------------------------------
// Kernel 2: left/right scalar projections, one warp per row.
// ---------------------------------------------------------------------------
__global__ void __launch_bounds__(256) lr_kernel(
    const float* __restrict__ h,
    const float* __restrict__ wlr, const float* __restrict__ blr,
    const float* __restrict__ wrl, const float* __restrict__ brl)
{
    const int row = blockIdx.x * 8 + (threadIdx.x >> 5);
    const int lane = threadIdx.x & 31;
    const float* hr = h + (size_t)row * DIN;
    float sl = 0.f, sr = 0.f;
    for (int d = lane; d < DIN; d += 32) {
        float hv = hr[d];
        sl = fmaf(hv, wlr[d], sl);
        sr = fmaf(hv, wrl[d], sr);
    }
#pragma unroll
    for (int o = 16; o; o >>= 1) {
        sl += __shfl_down_sync(0xFFFFFFFFu, sl, o);
        sr += __shfl_down_sync(0xFFFFFFFFu, sr, o);
    }
    if (lane == 0) {
        g_left[row]  = sl + blr[0];
        g_right[row] = sr + brl[0];
    }
}

// ---------------------------------------------------------------------------
// Kernel 3: scores = q @ k^T per batch + fused logsigmoid epilogue.
// Stores log_p = logsigmoid(raw) and log_1mp = logsigmoid(-raw).
// ---------------------------------------------------------------------------
__global__ void __launch_bounds__(256) scores_kernel(
    const float* __restrict__ alpha_p,
    const float* __restrict__ beta_p,
    const float* __restrict__ gamma_p)
{
    const int b = blockIdx.z;
    const float* __restrict__ Q = g_q + (size_t)b * NN * DM;
    const float* __restrict__ K = g_k + (size_t)b * NN * DM;

    __shared__ float As[16][68];
    __shared__ float Bs[16][68];

    const int m0 = blockIdx.y * 64;   // i tile
    const int o0 = blockIdx.x * 64;   // j tile
    const int tid = threadIdx.x;
    const int lr = tid >> 2;
    const int lc = tid & 3;
    const int tx = tid & 15;
    const int ty = tid >> 4;

    float acc[4][4];
#pragma unroll
    for (int a = 0; a < 4; a++)
#pragma unroll
        for (int c = 0; c < 4; c++) acc[a][c] = 0.f;

    for (int k0 = 0; k0 < DM; k0 += 16) {
        float4 av = *(const float4*)&Q[(size_t)(m0 + lr) * DM + k0 + lc * 4];
        float4 bv = *(const float4*)&K[(size_t)(o0 + lr) * DM + k0 + lc * 4];
        As[lc * 4 + 0][lr] = av.x; As[lc * 4 + 1][lr] = av.y;
        As[lc * 4 + 2][lr] = av.z; As[lc * 4 + 3][lr] = av.w;
        Bs[lc * 4 + 0][lr] = bv.x; Bs[lc * 4 + 1][lr] = bv.y;
        Bs[lc * 4 + 2][lr] = bv.z; Bs[lc * 4 + 3][lr] = bv.w;
        __syncthreads();
#pragma unroll
        for (int kk = 0; kk < 16; kk++) {
            float ar[4], br[4];
#pragma unroll
            for (int ii = 0; ii < 4; ii++) ar[ii] = As[kk][ty * 4 + ii];
#pragma unroll
            for (int jj = 0; jj < 4; jj++) br[jj] = Bs[kk][tx * 4 + jj];
#pragma unroll
            for (int ii = 0; ii < 4; ii++)
#pragma unroll
                for (int jj = 0; jj < 4; jj++)
                    acc[ii][jj] = fmaf(ar[ii], br[jj], acc[ii][jj]);
        }
        __syncthreads();
    }

    const float alpha = alpha_p[0];
    const float beta  = beta_p[0];
    const float gamma = gamma_p[0];

    float* lp_base  = g_logp   + (size_t)b * NN * NN;
    float* l1_base  = g_log1mp + (size_t)b * NN * NN;

#pragma unroll
    for (int ii = 0; ii < 4; ii++) {
        const int i = m0 + ty * 4 + ii;
        const float lft = g_left[b * NN + i];
        const float rgt = g_right[b * NN + i];
#pragma unroll
        for (int jj = 0; jj < 4; jj++) {
            const int j = o0 + tx * 4 + jj;
            const float dv = (j >= i) ? lft : rgt;
            float raw = alpha * acc[ii][jj] + beta * dv + gamma;
            raw = fminf(fmaxf(raw, -16.f), 14.f);
            // log sigmoid(raw) and log(1 - sigmoid(raw)); raw bounded so exp safe
            const float lp = -log1pf(expf(-raw));
            const float l1 = -log1pf(expf(raw));
            lp_base[(size_t)i * NN + j] = lp;
            l1_base[(size_t)i * NN + j] = l1;
        }
    }
}

// ---------------------------------------------------------------------------
// Kernel 4: per-(b,i) row: prefix sum of log_1mp -> interval sums -> r.
// The mask M[i,j,:] is a union of <=2 contiguous k-intervals:
//   i<j: (i, j) and [max(2i-j+1,0), i)
//   i>j: (j, i) and (i, min(2i-j, N-1)]
// so the einsum reduces to 4 prefix lookups.
// ---------------------------------------------------------------------------
__global__ void __launch_bounds__(NN) finalize_kernel(
    const float* __restrict__ mask,
    float* __restrict__ r_out,
    float* __restrict__ am_out)
{
    const int bi = blockIdx.x;           // b * N + i
    const int b = bi / NN;
    const int i = bi - b * NN;
    const int j = threadIdx.x;           // 0..383

    __shared__ float S[NN + 1];
    __shared__ float warpsum[12];

    const float v = g_log1mp[(size_t)bi * NN + j];

    // warp inclusive scan
    float x = v;
#pragma unroll
    for (int o = 1; o < 32; o <<= 1) {
        float y = __shfl_up_sync(0xFFFFFFFFu, x, o);
        if ((j & 31) >= o) x += y;
    }
    if ((j & 31) == 31) warpsum[j >> 5] = x;
    __syncthreads();
    if (j < 12) {
        float w = warpsum[j];
#pragma unroll
        for (int o = 1; o < 12; o <<= 1) {
            float y = __shfl_up_sync(0x00000FFFu, w, o);
            if (j >= o) w += y;
        }
        warpsum[j] = w;
    }
    __syncthreads();
    float incl = x + ((j >= 32) ? warpsum[(j >> 5) - 1] : 0.f);
    S[j + 1] = incl;
    if (j == 0) S[0] = 0.f;
    __syncthreads();

    const float lp = g_logp[(size_t)bi * NN + j];
    float a;
    if (i == j) {
        a = lp - 10000.f;
    } else if (i < j) {
        const int lo = max(2 * i - j + 1, 0);
        a = lp + (S[j] - S[i + 1]) + (S[i] - S[lo]);
    } else {
        const int hi = min(2 * i - j, NN - 1);
        a = lp + (S[i] - S[j + 1]) + (S[hi + 1] - S[i + 1]);
    }

    r_out[(size_t)bi * NN + j] = a;
    if (am_out) {
        am_out[(size_t)bi * NN + j] = mask[b * NN + i] * mask[b * NN + j];
    }
}

// ---------------------------------------------------------------------------
// Launch
// Inputs (metadata order): h, mask, Wq, bq, Wk, wlr, blr, wrl, brl,
//                          alpha, beta, gamma, masking_matrix
// Output: r (B*N*N) followed by alignment_mask (B*N*N) if room.
// ---------------------------------------------------------------------------
extern "C" void kernel_launch(void* const* d_in, const int* in_sizes, int n_in,
                              void* d_out, int out_size)
{
    const float* h     = (const float*)d_in[0];
    const float* mask  = (const float*)d_in[1];
    const float* Wq    = (const float*)d_in[2];
    const float* bq    = (const float*)d_in[3];
    const float* Wk    = (const float*)d_in[4];
    const float* wlr   = (const float*)d_in[5];
    const float* blr   = (const float*)d_in[6];
    const float* wrl   = (const float*)d_in[7];
    const float* brl   = (const float*)d_in[8];
    const float* alpha = (const float*)d_in[9];
    const float* beta  = (const float*)d_in[10];
    const float* gamma = (const float*)d_in[11];
    // d_in[12] = masking_matrix : unused (replaced by closed-form intervals)

    float* r_out = (float*)d_out;
    const long long BNN = (long long)BB * NN * NN;
    float* am_out = (out_size >= 2 * BNN) ? (r_out + BNN) : nullptr;

    // K1: q/k projections
    {
        dim3 grid(DM / 64, (BB * NN) / 64, 2);
        proj_gemm<<<grid, 256>>>(h, Wq, bq, Wk);
    }
    // K2: left/right
    {
        lr_kernel<<<(BB * NN) / 8, 256>>>(h, wlr, blr, wrl, brl);
    }
    // K3: scores + logsigmoid
    {
        dim3 grid(NN / 64, NN / 64, BB);
        scores_kernel<<<grid, 256>>>(alpha, beta, gamma);
    }
    // K4: scan + assembly
    {
        finalize_kernel<<<BB * NN, NN>>>(mask, r_out, am_out);
    }
}